// round 12
// baseline (speedup 1.0000x reference)
#include <cuda_runtime.h>

// Problem constants (shapes fixed by the dataset)
#define BATCH 64
#define FT    51200            // 80 * 640 elements per (channel,batch) slab
#define BFT   3276800          // 64*80*640 per-channel flattened length
#define NAUX  32
#define WPB   1600             // FT/32 bitset words per batch slab
#define NPAIR 2048             // NAUX * BATCH
#define NFIFTH 5               // aux slab split
#define F4_PER_FIFTH 2560      // 12800/5
#define AUX_F4_PER_WARP 320    // 2560/8 warps
#define AUX_NBLK (NPAIR * NFIFTH)   // 10240
#define STR_BLKS 1600          // blocks carrying a strain prologue (1 chunk/warp)
#define FULLM 0xffffffffu

// Largest float strictly below 20.0f: (x > TH_LT) <=> (x >= 20.0f)
#define TH_LT __int_as_float(0x419FFFFF)

// Scratch (__device__ globals — no allocations). Both bitsets are fully
// overwritten every launch -> deterministic across graph replays. No flags,
// no atomics: the kernel boundary is the only synchronization.
__device__ unsigned g_sbits[BATCH * WPB];        // strain peak bitset (410 KB)
__device__ unsigned g_abits[NPAIR * WPB];        // aux peak bitsets  (13.1 MB)

__device__ __forceinline__ float finf() { return __int_as_float(0x7f800000); }

__device__ __forceinline__ unsigned nib4(float4 v, float l, float r) {
    unsigned b0 = (v.x > fmaxf(fmaxf(l,   v.y), TH_LT)) ? 1u : 0u;
    unsigned b1 = (v.y > fmaxf(fmaxf(v.x, v.z), TH_LT)) ? 2u : 0u;
    unsigned b2 = (v.z > fmaxf(fmaxf(v.y, v.w), TH_LT)) ? 4u : 0u;
    unsigned b3 = (v.w > fmaxf(fmaxf(v.z, r),   TH_LT)) ? 8u : 0u;
    return (b0 | b1) | (b2 | b3);
}

// ---------------------------------------------------------------------------
// Kernel 1: pure streaming, zero synchronization. All 10240 blocks build
// their aux-slab peak bitset (word layout identical to g_sbits). Blocks
// 0..1599 first run one strain chunk per warp (the R9 loop-free form) —
// strain's 13MB rides along with the 419MB aux stream. No smem, no
// syncthreads, no reductions: partial-sum machinery is gone entirely.
// Occ cap 4 retained (L1tex-queue contention at occ 8 measured in R6).
// ---------------------------------------------------------------------------
__global__ __launch_bounds__(256, 4) void stream_kernel(const float* __restrict__ s,
                                                        const float* __restrict__ aux) {
    const int blk = blockIdx.x;
    const int tid = threadIdx.x, lane = tid & 31, w = tid >> 5;

    if (blk < STR_BLKS) {
        // ---- strain prologue: one 256-element chunk per warp ----
        const int chunk = blk * 8 + w;               // 0..12799
        const int q0 = chunk * 64;
        const int ge = q0 * 4;
        const float4* p4s = reinterpret_cast<const float4*>(s) + q0;

        const float4 v0 = p4s[2 * lane];
        const float4 v1 = p4s[2 * lane + 1];
        float l = __shfl_up_sync(FULLM, v1.w, 1);
        if (lane == 0)  l = (ge == 0) ? finf() : __ldg(s + ge - 1);
        float r = __shfl_down_sync(FULLM, v0.x, 1);
        if (lane == 31) r = (ge + 256 == BFT) ? finf() : __ldg(s + ge + 256);

        const unsigned byte = nib4(v0, l, v1.x) | (nib4(v1, v0.w, r) << 4);
        unsigned word = byte << ((lane & 3) << 3);
        word |= __shfl_xor_sync(FULLM, word, 1);
        word |= __shfl_xor_sync(FULLM, word, 2);
        if ((lane & 3) == 0) g_sbits[(ge >> 5) + (lane >> 2)] = word;
    }

    // ---- aux streaming + bitset emission ----
    const int pair = blk / NFIFTH, fifth = blk - pair * NFIFTH;
    const int b = pair & 63, n = pair >> 6;

    const float* ch = aux + (size_t)n * BFT;
    const int slab4 = fifth * F4_PER_FIFTH + w * AUX_F4_PER_WARP;  // in-slab f4 idx
    const int gelem = b * FT + slab4 * 4;
    const float4* p4 = reinterpret_cast<const float4*>(ch + gelem);
    // destination words for this warp: pair-slab word = slab4>>3 + it*4 + (lane>>3)
    unsigned* awp = g_abits + pair * WPB + (slab4 >> 3) + (lane >> 3);
    const int sh = (lane & 7) << 2;

    float carry = (gelem == 0) ? finf() : __ldg(ch + gelem - 1);
    const float rlast = (gelem + 4 * AUX_F4_PER_WARP == BFT)
                            ? finf()
                            : __ldg(ch + gelem + 4 * AUX_F4_PER_WARP);
    float4 v = __ldcs(&p4[lane]);
#pragma unroll
    for (int it = 0; it < 10; ++it) {
        float4 vn = v;
        if (it < 9) vn = __ldcs(&p4[(it + 1) * 32 + lane]);
        float l = __shfl_up_sync(FULLM, v.w, 1);
        if (lane == 0) l = carry;
        float r = __shfl_down_sync(FULLM, v.x, 1);
        float r31 = (it < 9) ? __shfl_sync(FULLM, vn.x, 0) : rlast;
        if (lane == 31) r = r31;
        carry = __shfl_sync(FULLM, v.w, 31);

        unsigned word = nib4(v, l, r) << sh;
        word |= __shfl_xor_sync(FULLM, word, 1);
        word |= __shfl_xor_sync(FULLM, word, 2);
        word |= __shfl_xor_sync(FULLM, word, 4);
        if ((lane & 7) == 0) awp[it * 4] = word;     // stays L2-resident for k2
        v = vn;
    }
}

// ---------------------------------------------------------------------------
// Kernel 2: per-pair combine + finalize. 2048 blocks x 256 threads. Reads the
// just-written aux bitset (L2) and the strain bitset (L2, shared x32), does
// popc(a&s)/popc(a)/popc(s), block-reduces, emits jaccard + ratio directly.
// c1 is counted exactly once per word (no replication factor).
// ---------------------------------------------------------------------------
__global__ __launch_bounds__(256) void combine_kernel(float* __restrict__ out,
                                                      int half) {
    const int pair = blockIdx.x;                     // == n*64 + b == output idx
    const int b = pair & 63;
    const int tid = threadIdx.x, lane = tid & 31, w = tid >> 5;

    const unsigned* __restrict__ ap = g_abits + pair * WPB;
    const unsigned* __restrict__ sp = g_sbits + b * WPB;

    int inter = 0, c2 = 0, c1 = 0;
#pragma unroll
    for (int k = 0; k < 7; ++k) {                    // 7*256 >= 1600
        const int i = k * 256 + tid;
        if (i < WPB) {
            unsigned a = __ldg(ap + i);
            unsigned s = __ldg(sp + i);
            inter += __popc(a & s);
            c2    += __popc(a);
            c1    += __popc(s);
        }
    }

    __shared__ int sm0[8], sm1[8], sm2[8];
#pragma unroll
    for (int o = 16; o > 0; o >>= 1) {
        inter += __shfl_down_sync(FULLM, inter, o);
        c2    += __shfl_down_sync(FULLM, c2, o);
        c1    += __shfl_down_sync(FULLM, c1, o);
    }
    if (lane == 0) { sm0[w] = inter; sm1[w] = c2; sm2[w] = c1; }
    __syncthreads();
    if (tid == 0) {
        int ti = 0, tc = 0, ta = 0;
#pragma unroll
        for (int k = 0; k < 8; ++k) { ti += sm0[k]; tc += sm1[k]; ta += sm2[k]; }
        const int uni = ta + tc - ti;
        float jac, ratio;
        if (uni == 0) {
            jac = 1.0f; ratio = 1.0f;                // empty-vs-empty
        } else {
            jac = (float)ti / (float)uni;
            ratio = (ta == 0) ? 0.0f : (float)ti / (float)ta;  // nan_to_num(0/0)->0
        }
        out[pair] = jac;
        out[half + pair] = ratio;
    }
}

extern "C" void kernel_launch(void* const* d_in, const int* in_sizes, int n_in,
                              void* d_out, int out_size) {
    const float* strain = (const float*)d_in[0];
    const float* aux    = (const float*)d_in[1];
    if (n_in >= 2 && in_sizes[0] != BFT) {           // defensive order check
        strain = (const float*)d_in[1];
        aux    = (const float*)d_in[0];
    }
    float* out = (float*)d_out;

    stream_kernel<<<AUX_NBLK, 256>>>(strain, aux);
    combine_kernel<<<NPAIR, 256>>>(out, out_size >> 1);
}

// round 13
// speedup vs baseline: 1.0376x; 1.0376x over previous
#include <cuda_runtime.h>

// Problem constants (shapes fixed by the dataset)
#define BATCH 64
#define FT    51200            // 80 * 640 elements per (channel,batch) slab
#define BFT   3276800          // 64*80*640 per-channel flattened length
#define NAUX  32
#define WPB   1600             // FT/32 bitset words per batch
#define NPAIR 2048             // NAUX * BATCH
#define NFIFTH 5               // aux slab split
#define F4_PER_FIFTH 2560      // 12800/5
#define AUX_F4_PER_WARP 320    // 2560/8 warps
#define AUX_NBLK (NPAIR * NFIFTH)   // 10240
#define STR_NBLK 1600          // 12800 warps x 256 elems = 3276800
#define FULLM 0xffffffffu

// Largest float strictly below 20.0f: (x > TH_LT) <=> (x >= 20.0f)
#define TH_LT __int_as_float(0x419FFFFF)

// Scratch (__device__ globals — no allocations). Partials are TRANSPOSED
// [fifth][pair] so fin's loads coalesce across threads (R10/R11 profiled the
// strided fin at 5.1-5.3us, latency-bound at grid=2). Fully overwritten every
// launch -> deterministic across graph replays.
__device__ unsigned g_sbits[BATCH * WPB];
__device__ int g_pi[NFIFTH * NPAIR];   // partial intersections
__device__ int g_pc[NFIFTH * NPAIR];   // partial aux peak counts
__device__ int g_pa[NFIFTH * NPAIR];   // partial 8*c1 accumulators

__device__ __forceinline__ float finf() { return __int_as_float(0x7f800000); }

__device__ __forceinline__ unsigned nib4(float4 v, float l, float r) {
    unsigned b0 = (v.x > fmaxf(fmaxf(l,   v.y), TH_LT)) ? 1u : 0u;
    unsigned b1 = (v.y > fmaxf(fmaxf(v.x, v.z), TH_LT)) ? 2u : 0u;
    unsigned b2 = (v.z > fmaxf(fmaxf(v.y, v.w), TH_LT)) ? 4u : 0u;
    unsigned b3 = (v.w > fmaxf(fmaxf(v.z, r),   TH_LT)) ? 8u : 0u;
    return (b0 | b1) | (b2 | b3);
}

// ---------------------------------------------------------------------------
// Strain kernel: loop-free (R9 form) at occ cap 4 — the fastest measured
// strain (R4, 6.08us) ran cap 4; cap-4-beats-cap-8 matches the L1tex-queue
// contention law measured on aux in R6. 1600 blocks x 256 threads; each
// thread owns 8 contiguous elements (2 float4 loads), 2 shuffles for
// cross-thread neighbors, 2 shfl_xor to assemble each word.
// ---------------------------------------------------------------------------
__global__ __launch_bounds__(256, 4) void strain_kernel(const float* __restrict__ s) {
    const int tid = threadIdx.x, lane = tid & 31, w = tid >> 5;
    const int warp_id = blockIdx.x * 8 + w;          // 0..12799
    const int q0 = warp_id * 64;                     // first float4 of warp
    const int gelem = q0 * 4;                        // 256 elements per warp
    const float4* p4 = reinterpret_cast<const float4*>(s) + q0;

    const float4 v0 = p4[2 * lane];
    const float4 v1 = p4[2 * lane + 1];

    float l = __shfl_up_sync(FULLM, v1.w, 1);
    if (lane == 0)  l = (gelem == 0) ? finf() : __ldg(s + gelem - 1);
    float r = __shfl_down_sync(FULLM, v0.x, 1);
    if (lane == 31) r = (gelem + 256 == BFT) ? finf() : __ldg(s + gelem + 256);

    const unsigned byte = nib4(v0, l, v1.x) | (nib4(v1, v0.w, r) << 4);
    unsigned word = byte << ((lane & 3) << 3);
    word |= __shfl_xor_sync(FULLM, word, 1);
    word |= __shfl_xor_sync(FULLM, word, 2);
    if ((lane & 3) == 0) g_sbits[(gelem >> 5) + (lane >> 2)] = word;
}

// ---------------------------------------------------------------------------
// Aux kernel: byte-identical to the R9 version (triple-proven ~58us, ~88% of
// DRAM spec) except the partial-store indices, which are now transposed.
// 10240 blocks (2048 pairs x 5 fifths), 256 threads, occ cap 4 (LOAD-BEARING,
// R6), __ldcs streaming, plain partial stores, no atomics/fences.
// ---------------------------------------------------------------------------
__global__ __launch_bounds__(256, 4) void aux_kernel(const float* __restrict__ aux) {
    const int blk = blockIdx.x;
    const int pair = blk / NFIFTH, fifth = blk - pair * NFIFTH;
    const int b = pair & 63, n = pair >> 6;
    const int tid = threadIdx.x, lane = tid & 31, w = tid >> 5;

    const float* ch = aux + (size_t)n * BFT;
    const int slab4 = fifth * F4_PER_FIFTH + w * AUX_F4_PER_WARP;
    const int gelem = b * FT + slab4 * 4;
    const float4* p4 = reinterpret_cast<const float4*>(ch + gelem);
    const unsigned* __restrict__ swp = g_sbits + b * WPB + (slab4 >> 3) + (lane >> 3);
    const int sh = (lane & 7) << 2;

    float carry = (gelem == 0) ? finf() : __ldg(ch + gelem - 1);
    const float rlast = (gelem + 4 * AUX_F4_PER_WARP == BFT)
                            ? finf()
                            : __ldg(ch + gelem + 4 * AUX_F4_PER_WARP);
    int inter = 0, c2 = 0, c1a = 0;
    float4 v = __ldcs(&p4[lane]);
#pragma unroll
    for (int it = 0; it < 10; ++it) {
        float4 vn = v;
        if (it < 9) vn = __ldcs(&p4[(it + 1) * 32 + lane]);
        float l = __shfl_up_sync(FULLM, v.w, 1);
        if (lane == 0) l = carry;
        float r = __shfl_down_sync(FULLM, v.x, 1);
        float r31 = (it < 9) ? __shfl_sync(FULLM, vn.x, 0) : rlast;
        if (lane == 31) r = r31;
        carry = __shfl_sync(FULLM, v.w, 31);

        unsigned nib = nib4(v, l, r);
        unsigned sw = __ldg(swp + it * 4);            // 8 lanes broadcast same word
        inter += __popc((sw >> sh) & nib);
        c2 += __popc(nib);
        c1a += __popc(sw);                            // sums to 8*c1 over the slab
        v = vn;
    }

    // Block reduce 3 ints (8 warps).
    __shared__ int sm0[8], sm1[8], sm2[8];
#pragma unroll
    for (int o = 16; o > 0; o >>= 1) {
        inter += __shfl_down_sync(FULLM, inter, o);
        c2    += __shfl_down_sync(FULLM, c2, o);
        c1a   += __shfl_down_sync(FULLM, c1a, o);
    }
    if (lane == 0) { sm0[w] = inter; sm1[w] = c2; sm2[w] = c1a; }
    __syncthreads();
    if (tid == 0) {
        int a = 0, bb = 0, c = 0;
#pragma unroll
        for (int k = 0; k < 8; ++k) { a += sm0[k]; bb += sm1[k]; c += sm2[k]; }
        const int pidx = fifth * NPAIR + pair;        // transposed for coalesced fin
        g_pi[pidx] = a; g_pc[pidx] = bb; g_pa[pidx] = c;
    }
}

// ---------------------------------------------------------------------------
// Finalize: 8 blocks x 256 threads, one thread per pair. With the transposed
// partial layout, all 15 loads per thread are fully coalesced across the
// block (stride-1 in pair index).
// ---------------------------------------------------------------------------
__global__ __launch_bounds__(256) void fin_kernel(float* __restrict__ out, int half) {
    const int idx = blockIdx.x * 256 + threadIdx.x;   // pair id, 0..2047
    int ti = 0, tc = 0, ta = 0;
#pragma unroll
    for (int k = 0; k < NFIFTH; ++k) {
        ti += g_pi[k * NPAIR + idx];
        tc += g_pc[k * NPAIR + idx];
        ta += g_pa[k * NPAIR + idx];
    }
    const int c1 = ta >> 3;
    const int uni = c1 + tc - ti;
    float jac, ratio;
    if (uni == 0) {
        jac = 1.0f; ratio = 1.0f;                     // empty-vs-empty
    } else {
        jac = (float)ti / (float)uni;
        ratio = (c1 == 0) ? 0.0f : (float)ti / (float)c1;  // nan_to_num(0/0)->0
    }
    out[idx] = jac;
    out[half + idx] = ratio;
}

extern "C" void kernel_launch(void* const* d_in, const int* in_sizes, int n_in,
                              void* d_out, int out_size) {
    const float* strain = (const float*)d_in[0];
    const float* aux    = (const float*)d_in[1];
    if (n_in >= 2 && in_sizes[0] != BFT) {            // defensive order check
        strain = (const float*)d_in[1];
        aux    = (const float*)d_in[0];
    }
    float* out = (float*)d_out;

    strain_kernel<<<STR_NBLK, 256>>>(strain);
    aux_kernel<<<AUX_NBLK, 256>>>(aux);
    fin_kernel<<<NPAIR / 256, 256>>>(out, out_size >> 1);
}

// round 14
// speedup vs baseline: 1.1609x; 1.1188x over previous
#include <cuda_runtime.h>

// Problem constants (shapes fixed by the dataset)
#define BATCH 64
#define FT    51200            // 80 * 640 elements per (channel,batch) slab
#define BFT   3276800          // 64*80*640 per-channel flattened length
#define NAUX  32
#define WPB   1600             // FT/32 bitset words per batch
#define NPAIR 2048             // NAUX * BATCH
#define NFIFTH 5               // aux slab split
#define F4_PER_FIFTH 2560      // 12800/5
#define AUX_F4_PER_WARP 320    // 2560/8 warps
#define AUX_NBLK (NPAIR * NFIFTH)   // 10240
#define STR_NBLK 1600          // 12800 warps x 256 elems = 3276800
#define FULLM 0xffffffffu

// Largest float strictly below 20.0f: (x > TH_LT) <=> (x >= 20.0f)
#define TH_LT __int_as_float(0x419FFFFF)

// Scratch (__device__ globals — no allocations). All partials fully
// overwritten every launch -> deterministic across graph replays.
__device__ unsigned g_sbits[BATCH * WPB];
__device__ int g_pi[AUX_NBLK];   // partial intersections
__device__ int g_pc[AUX_NBLK];   // partial aux peak counts
__device__ int g_pa[AUX_NBLK];   // partial 8*c1 accumulators

__device__ __forceinline__ float finf() { return __int_as_float(0x7f800000); }

__device__ __forceinline__ unsigned nib4(float4 v, float l, float r) {
    unsigned b0 = (v.x > fmaxf(fmaxf(l,   v.y), TH_LT)) ? 1u : 0u;
    unsigned b1 = (v.y > fmaxf(fmaxf(v.x, v.z), TH_LT)) ? 2u : 0u;
    unsigned b2 = (v.z > fmaxf(fmaxf(v.y, v.w), TH_LT)) ? 4u : 0u;
    unsigned b3 = (v.w > fmaxf(fmaxf(v.z, r),   TH_LT)) ? 8u : 0u;
    return (b0 | b1) | (b2 | b3);
}

// ---------------------------------------------------------------------------
// Strain kernel: loop-free, chain-free. Each thread owns 8 contiguous
// elements (2 float4 loads) -> interior neighbors in-register; exactly 2
// shuffles for cross-thread neighbors, 2 scalar loads per warp for warp
// edges, 2 shfl_xor to assemble each 32-bit word from 4 lanes.
// 1600 blocks x 256 threads.
// ---------------------------------------------------------------------------
__global__ __launch_bounds__(256, 8) void strain_kernel(const float* __restrict__ s) {
    const int tid = threadIdx.x, lane = tid & 31, w = tid >> 5;
    const int warp_id = blockIdx.x * 8 + w;          // 0..12799
    const int q0 = warp_id * 64;                     // first float4 of warp
    const int gelem = q0 * 4;                        // first element of warp (256/warp)
    const float4* p4 = reinterpret_cast<const float4*>(s) + q0;

    const float4 v0 = p4[2 * lane];
    const float4 v1 = p4[2 * lane + 1];

    float l = __shfl_up_sync(FULLM, v1.w, 1);
    if (lane == 0)  l = (gelem == 0) ? finf() : __ldg(s + gelem - 1);
    float r = __shfl_down_sync(FULLM, v0.x, 1);
    if (lane == 31) r = (gelem + 256 == BFT) ? finf() : __ldg(s + gelem + 256);

    const unsigned byte = nib4(v0, l, v1.x) | (nib4(v1, v0.w, r) << 4);
    unsigned word = byte << ((lane & 3) << 3);
    word |= __shfl_xor_sync(FULLM, word, 1);
    word |= __shfl_xor_sync(FULLM, word, 2);
    if ((lane & 3) == 0) g_sbits[(gelem >> 5) + (lane >> 2)] = word;
}

// ---------------------------------------------------------------------------
// Aux kernel: 10240 blocks (2048 pairs x 5 fifths), 256 threads, occ cap 4
// (LOAD-BEARING: occ-8 measured DRAM 68.7% vs occ-4 ~73-88% — cross-CTA
// L1tex-queue contention). Plain partial stores, no atomics/fences (fused
// ticket+finalize measured ~6us slower in R7).
// ---------------------------------------------------------------------------
__global__ __launch_bounds__(256, 4) void aux_kernel(const float* __restrict__ aux) {
    const int blk = blockIdx.x;
    const int pair = blk / NFIFTH, fifth = blk - pair * NFIFTH;
    const int b = pair & 63, n = pair >> 6;
    const int tid = threadIdx.x, lane = tid & 31, w = tid >> 5;

    const float* ch = aux + (size_t)n * BFT;
    const int slab4 = fifth * F4_PER_FIFTH + w * AUX_F4_PER_WARP;
    const int gelem = b * FT + slab4 * 4;
    const float4* p4 = reinterpret_cast<const float4*>(ch + gelem);
    const unsigned* __restrict__ swp = g_sbits + b * WPB + (slab4 >> 3) + (lane >> 3);
    const int sh = (lane & 7) << 2;

    float carry = (gelem == 0) ? finf() : __ldg(ch + gelem - 1);
    const float rlast = (gelem + 4 * AUX_F4_PER_WARP == BFT)
                            ? finf()
                            : __ldg(ch + gelem + 4 * AUX_F4_PER_WARP);
    int inter = 0, c2 = 0, c1a = 0;
    float4 v = __ldcs(&p4[lane]);
#pragma unroll
    for (int it = 0; it < 10; ++it) {
        float4 vn = v;
        if (it < 9) vn = __ldcs(&p4[(it + 1) * 32 + lane]);
        float l = __shfl_up_sync(FULLM, v.w, 1);
        if (lane == 0) l = carry;
        float r = __shfl_down_sync(FULLM, v.x, 1);
        float r31 = (it < 9) ? __shfl_sync(FULLM, vn.x, 0) : rlast;
        if (lane == 31) r = r31;
        carry = __shfl_sync(FULLM, v.w, 31);

        unsigned nib = nib4(v, l, r);
        unsigned sw = __ldg(swp + it * 4);            // 8 lanes broadcast same word
        inter += __popc((sw >> sh) & nib);
        c2 += __popc(nib);
        c1a += __popc(sw);                            // sums to 8*c1 over the slab
        v = vn;
    }

    // Block reduce 3 ints (8 warps).
    __shared__ int sm0[8], sm1[8], sm2[8];
#pragma unroll
    for (int o = 16; o > 0; o >>= 1) {
        inter += __shfl_down_sync(FULLM, inter, o);
        c2    += __shfl_down_sync(FULLM, c2, o);
        c1a   += __shfl_down_sync(FULLM, c1a, o);
    }
    if (lane == 0) { sm0[w] = inter; sm1[w] = c2; sm2[w] = c1a; }
    __syncthreads();
    if (tid == 0) {
        int a = 0, bb = 0, c = 0;
#pragma unroll
        for (int k = 0; k < 8; ++k) { a += sm0[k]; bb += sm1[k]; c += sm2[k]; }
        g_pi[blk] = a; g_pc[blk] = bb; g_pa[blk] = c;
    }
}

// ---------------------------------------------------------------------------
// Finalize: 2048 threads; sum 5 partials each, emit jaccard + ratio.
// ---------------------------------------------------------------------------
__global__ void fin_kernel(float* __restrict__ out, int half) {
    const int idx = blockIdx.x * blockDim.x + threadIdx.x;
    if (idx >= NPAIR) return;
    int ti = 0, tc = 0, ta = 0;
#pragma unroll
    for (int k = 0; k < NFIFTH; ++k) {
        ti += g_pi[idx * NFIFTH + k];
        tc += g_pc[idx * NFIFTH + k];
        ta += g_pa[idx * NFIFTH + k];
    }
    const int c1 = ta >> 3;
    const int uni = c1 + tc - ti;
    float jac, ratio;
    if (uni == 0) {
        jac = 1.0f; ratio = 1.0f;                     // empty-vs-empty
    } else {
        jac = (float)ti / (float)uni;
        ratio = (c1 == 0) ? 0.0f : (float)ti / (float)c1;  // nan_to_num(0/0)->0
    }
    out[idx] = jac;
    out[half + idx] = ratio;
}

extern "C" void kernel_launch(void* const* d_in, const int* in_sizes, int n_in,
                              void* d_out, int out_size) {
    const float* strain = (const float*)d_in[0];
    const float* aux    = (const float*)d_in[1];
    if (n_in >= 2 && in_sizes[0] != BFT) {            // defensive order check
        strain = (const float*)d_in[1];
        aux    = (const float*)d_in[0];
    }
    float* out = (float*)d_out;

    strain_kernel<<<STR_NBLK, 256>>>(strain);
    aux_kernel<<<AUX_NBLK, 256>>>(aux);
    fin_kernel<<<2, 1024>>>(out, out_size >> 1);
}